// round 16
// baseline (speedup 1.0000x reference)
#include <cuda_runtime.h>
#include <cuda_fp16.h>
#include <math.h>
#include <stddef.h>
#include <stdint.h>

#define Bb   32
#define Hh   56
#define Ww   56
#define Cc   192
#define WS   7
#define SS   3
#define NHd  6
#define Nn   49
#define HD   32
#define NWTOT 2048
#define TOK  100352
#define HID  768
#define SCALE 0.17677669529663687f  /* 32^-0.5 */

// ---------------- scratch (device globals; no allocations) ----------------
__device__ __half g_qkv16 [(size_t)TOK * 3 * Cc];
__device__ __half g_attn16[(size_t)TOK * Cc];
__device__ float  g_h     [(size_t)TOK * Cc];
__device__ __half g_h16   [(size_t)TOK * Cc];
__device__ __half g_act16 [(size_t)TOK * HID];
__device__ __half g_qkvw16[3 * Cc * Cc];
__device__ __half g_projw16[Cc * Cc];
__device__ __half g_fc1w16[HID * Cc];
__device__ __half g_fc2w16[Cc * HID];
__device__ float  g_tab   [24 * 64 * 64];     // (cls*6+nh) x 64 x 64 bias+mask

// ---------------- helpers ----------------
static __device__ __forceinline__ uint32_t smem_u32(const void* p) {
    uint32_t a;
    asm("{ .reg .u64 t; cvta.to.shared.u64 t, %1; cvt.u32.u64 %0, t; }" : "=r"(a) : "l"(p));
    return a;
}
static __device__ __forceinline__ void ldsm4(uint32_t& r0, uint32_t& r1, uint32_t& r2,
                                             uint32_t& r3, uint32_t addr) {
    asm volatile("ldmatrix.sync.aligned.m8n8.x4.shared.b16 {%0,%1,%2,%3}, [%4];"
                 : "=r"(r0), "=r"(r1), "=r"(r2), "=r"(r3) : "r"(addr));
}
static __device__ __forceinline__ void mma_f16(float* c, const uint32_t* a, const uint32_t* b) {
    asm volatile(
        "mma.sync.aligned.m16n8k16.row.col.f32.f16.f16.f32 "
        "{%0,%1,%2,%3}, {%4,%5,%6,%7}, {%8,%9}, {%0,%1,%2,%3};"
        : "+f"(c[0]), "+f"(c[1]), "+f"(c[2]), "+f"(c[3])
        : "r"(a[0]), "r"(a[1]), "r"(a[2]), "r"(a[3]), "r"(b[0]), "r"(b[1]));
}
static __device__ __forceinline__ void cpa16(uint32_t dst, const void* src) {
    asm volatile("cp.async.ca.shared.global [%0], [%1], 16;" :: "r"(dst), "l"(src));
}
static __device__ __forceinline__ uint32_t h2u(float a, float b) {
    __half2 h = __floats2half2_rn(a, b);
    return *(uint32_t*)&h;
}
#define DIV7(u) (((u) * 9363) >> 16)

// ---------------- fused weight conversion + bias/mask tables ----------------
__global__ void cvt_all(const float* __restrict__ qkvw, const float* __restrict__ projw,
                        const float* __restrict__ fc1w, const float* __restrict__ fc2w,
                        const float* __restrict__ rpb) {
    int i = blockIdx.x * 256 + threadIdx.x;
    const int S0 = 3 * Cc * Cc, S1 = Cc * Cc, S2 = HID * Cc, S3 = Cc * HID;
    if (i < S0) { g_qkvw16[i] = __float2half(qkvw[i]); return; }
    i -= S0;
    if (i < S1) { g_projw16[i] = __float2half(projw[i]); return; }
    i -= S1;
    if (i < S2) { g_fc1w16[i] = __float2half(fc1w[i]); return; }
    i -= S2;
    if (i < S3) { g_fc2w16[i] = __float2half(fc2w[i]); return; }
    i -= S3;
    if (i < 24 * 4096) {
        int tb = i >> 12, idx = i & 4095;
        int cls = tb / NHd, nh = tb - cls * NHd;
        int lastR = (cls >> 1) & 1, lastC = cls & 1;
        int rI = idx >> 6, m = idx & 63;
        float v;
        if (rI >= Nn) v = 0.0f;
        else if (m >= Nn) v = -1e30f;
        else {
            int r1 = DIV7(rI), c1 = rI - r1 * 7;
            int r2 = DIV7(m),  c2 = m  - r2 * 7;
            float bias = rpb[((r1 - r2 + 6) * 13 + (c1 - c2 + 6)) * NHd + nh];
            int rg1 = (lastR ? (r1 < 4 ? 1 : 2) : 0) * 3 + (lastC ? (c1 < 4 ? 1 : 2) : 0);
            int rg2 = (lastR ? (r2 < 4 ? 1 : 2) : 0) * 3 + (lastC ? (c2 < 4 ? 1 : 2) : 0);
            v = bias + ((rg1 == rg2) ? 0.0f : -100.0f);
        }
        g_tab[(size_t)tb * 4096 + idx] = v;
    }
}

// ---------------- K-resident-A GEMM (K=192) with fused LayerNorm on A ----------------
// BM=256, n-loop NCH x 64; A tile resident (pitch 200 halves); B double-buffered.
// 256 thr, 8 warps (4m x 2n), warp tile 64x32.
// MODE 0 (qkv): A = x fp32, gathered (roll+window partition), LN1 fused.
//               epilogue: +bias, cols<192 * SCALE -> fp16
// MODE 1 (fc1): A = g_h16 fp16 rows, LN2 fused. epilogue: +bias, GELU -> fp16
#define KR_SMEM (256 * 400 + 2 * 64 * 400)
template <int NCH, int MODE>
__global__ void __launch_bounds__(256)
gemm_kr(const void* __restrict__ Asrc, const __half* __restrict__ Wt,
        const float* __restrict__ bias,
        const float* __restrict__ lng, const float* __restrict__ lnb,
        __half* __restrict__ Cout) {
    extern __shared__ __align__(16) char smem[];
    const int Nc  = NCH * 64;
    const int tid = threadIdx.x;
    const int wid = tid >> 5, lane = tid & 31;
    const int gp  = lane >> 2, tg = lane & 3;
    const int m0  = blockIdx.x << 8;
    const int wm  = (wid & 3) << 6;    // 0/64/128/192
    const int wn  = (wid >> 2) << 5;   // 0/32

    const uint32_t sA = smem_u32(smem);
    const uint32_t sB = sA + 256 * 400;
    __half* arow = (__half*)smem + tid * 200;

    // ---- B chunk 0 prefetch first (overlaps with A work) ----
    const int bLRow = tid >> 2, bQ = tid & 3;
    {
        const __half* src = Wt + (size_t)bLRow * Cc + bQ * 48;
        uint32_t dst = sB + bLRow * 400 + bQ * 96;
        #pragma unroll
        for (int s = 0; s < 6; s++) cpa16(dst + s * 16, src + s * 8);
    }
    if (MODE == 1) {
        // A row via cp.async (fp16 source)
        const __half* src = (const __half*)Asrc + (size_t)(m0 + tid) * Cc;
        uint32_t dst = sA + tid * 400;
        #pragma unroll
        for (int s = 0; s < 24; s++) cpa16(dst + s * 16, src + s * 8);
    }
    asm volatile("cp.async.commit_group;" ::: "memory");

    // ---- A tile + fused LayerNorm (each thread owns its row) ----
    float mean, inv;
    if (MODE == 0) {
        // gather + LN1 stats during fp32 load
        const int row = m0 + tid;
        int wi = row / Nn, n = row - wi * Nn;
        int bi = wi >> 6, wl = wi & 63;
        int wr = wl >> 3, wc = wl & 7;
        int r = DIV7(n), c2 = n - r * 7;
        int hs = (wr * 7 + r + SS) % Hh;
        int ws2 = (wc * 7 + c2 + SS) % Ww;
        const float4* src = (const float4*)((const float*)Asrc +
                            ((size_t)bi * (Hh * Ww) + hs * Ww + ws2) * Cc);
        float sum = 0.0f, sq = 0.0f;
        #pragma unroll 8
        for (int s = 0; s < 48; s++) {
            float4 v = __ldg(src + s);
            sum += v.x + v.y + v.z + v.w;
            sq  += v.x * v.x + v.y * v.y + v.z * v.z + v.w * v.w;
            *(__half2*)(arow + s * 4)     = __floats2half2_rn(v.x, v.y);
            *(__half2*)(arow + s * 4 + 2) = __floats2half2_rn(v.z, v.w);
        }
        mean = sum * (1.0f / Cc);
        inv  = rsqrtf(sq * (1.0f / Cc) - mean * mean + 1e-5f);
    } else {
        asm volatile("cp.async.wait_group 0;" ::: "memory");
        float sum = 0.0f, sq = 0.0f;
        #pragma unroll 6
        for (int s = 0; s < 24; s++) {
            uint4 pk = *(const uint4*)(arow + s * 8);
            const __half2* hp = (const __half2*)&pk;
            #pragma unroll
            for (int q = 0; q < 4; q++) {
                float lo = __low2float(hp[q]), hi = __high2float(hp[q]);
                sum += lo + hi;
                sq  += lo * lo + hi * hi;
            }
        }
        mean = sum * (1.0f / Cc);
        inv  = rsqrtf(sq * (1.0f / Cc) - mean * mean + 1e-5f);
    }
    // normalize in place
    #pragma unroll 6
    for (int s = 0; s < 24; s++) {
        uint4 pk = *(const uint4*)(arow + s * 8);
        const __half2* hp = (const __half2*)&pk;
        float4 g0 = __ldg((const float4*)(lng + s * 8));
        float4 g1 = __ldg((const float4*)(lng + s * 8 + 4));
        float4 b0 = __ldg((const float4*)(lnb + s * 8));
        float4 b1 = __ldg((const float4*)(lnb + s * 8 + 4));
        float gg[8] = {g0.x, g0.y, g0.z, g0.w, g1.x, g1.y, g1.z, g1.w};
        float bb[8] = {b0.x, b0.y, b0.z, b0.w, b1.x, b1.y, b1.z, b1.w};
        __half2 ot[4];
        #pragma unroll
        for (int q = 0; q < 4; q++) {
            float lo = (__low2float(hp[q])  - mean) * inv * gg[2 * q]     + bb[2 * q];
            float hi = (__high2float(hp[q]) - mean) * inv * gg[2 * q + 1] + bb[2 * q + 1];
            ot[q] = __floats2half2_rn(lo, hi);
        }
        *(uint4*)(arow + s * 8) = *(uint4*)ot;
    }

    const int aRow  = lane & 15;
    const int aCol8 = (lane >> 4) << 3;
    const int bRow  = ((lane & 16) >> 1) + (lane & 7);
    const int bCol8 = lane & 8;
    const uint32_t aBase0 = sA + (((wm + aRow) * 200 + aCol8) << 1);
    const uint32_t bOff   = (((wn + bRow) * 200 + bCol8) << 1);

    for (int ncx = 0; ncx < NCH; ncx++) {
        if (ncx + 1 < NCH) {
            const __half* src = Wt + (size_t)((ncx + 1) * 64 + bLRow) * Cc + bQ * 48;
            uint32_t dst = sB + (((ncx + 1) & 1) ? 64 * 400 : 0) + bLRow * 400 + bQ * 96;
            #pragma unroll
            for (int s = 0; s < 6; s++) cpa16(dst + s * 16, src + s * 8);
            asm volatile("cp.async.commit_group;" ::: "memory");
            asm volatile("cp.async.wait_group 1;" ::: "memory");
        } else {
            asm volatile("cp.async.wait_group 0;" ::: "memory");
        }
        __syncthreads();

        float acc[4][4][4];
        #pragma unroll
        for (int i = 0; i < 4; i++)
            #pragma unroll
            for (int j = 0; j < 4; j++)
                #pragma unroll
                for (int e = 0; e < 4; e++) acc[i][j][e] = 0.0f;

        const uint32_t bB = sB + ((ncx & 1) ? 64 * 400 : 0) + bOff;
        #pragma unroll
        for (int kk = 0; kk < 12; kk++) {
            uint32_t af[4][4];
            #pragma unroll
            for (int i = 0; i < 4; i++)
                ldsm4(af[i][0], af[i][1], af[i][2], af[i][3],
                      aBase0 + ((i * 16 * 200 + kk * 16) << 1));
            uint32_t bf[4][2];
            ldsm4(bf[0][0], bf[0][1], bf[1][0], bf[1][1], bB + ((kk * 16) << 1));
            ldsm4(bf[2][0], bf[2][1], bf[3][0], bf[3][1], bB + ((16 * 200 + kk * 16) << 1));
            #pragma unroll
            for (int i = 0; i < 4; i++)
                #pragma unroll
                for (int j = 0; j < 4; j++)
                    mma_f16(acc[i][j], af[i], bf[j]);
        }

        // epilogue for this n-chunk
        #pragma unroll
        for (int i = 0; i < 4; i++) {
            #pragma unroll
            for (int half = 0; half < 2; half++) {
                const int row = m0 + wm + (i << 4) + gp + (half << 3);
                size_t rowoff = (size_t)row * Nc;
                #pragma unroll
                for (int j = 0; j < 4; j++) {
                    const int ncol = ncx * 64 + wn + (j << 3) + (tg << 1);
                    float v0 = acc[i][j][half * 2 + 0] + bias[ncol + 0];
                    float v1 = acc[i][j][half * 2 + 1] + bias[ncol + 1];
                    if (MODE == 0 && ncol < Cc) { v0 *= SCALE; v1 *= SCALE; }
                    if (MODE == 1) {
                        v0 = 0.5f * v0 * (1.0f + erff(v0 * 0.70710678118654752f));
                        v1 = 0.5f * v1 * (1.0f + erff(v1 * 0.70710678118654752f));
                    }
                    *(__half2*)(Cout + rowoff + ncol) = __floats2half2_rn(v0, v1);
                }
            }
        }
        __syncthreads();   // protect B buffer before next prefetch overwrite
    }
}

// ---------------- BM=256, BN=64, BK=32; 256 thr, 2-stage (proj, fc2) ----------------
// EPI: 2 = +bias, scatter window->token, +resid -> fp32 h AND fp16 h16 (proj)
//      3 = +bias, +resid -> fp32 (fc2)
template <int EPI>
__global__ void __launch_bounds__(256)
gemm_b256(const __half* __restrict__ A, const __half* __restrict__ Wt,
          const float* __restrict__ bias, const float* __restrict__ resid,
          void* __restrict__ Cout, int Nc, int K) {
    __shared__ __half As[2][256 * 40];
    __shared__ __half Bs[2][64 * 40];

    const int tid  = threadIdx.x;
    const int wid  = tid >> 5, lane = tid & 31;
    const int gp   = lane >> 2, tg = lane & 3;
    const int m0   = blockIdx.y << 8;
    const int n0   = blockIdx.x << 6;
    const int wm   = (wid & 3) << 6;    // 0/64/128/192
    const int wn   = (wid >> 2) << 5;   // 0/32

    float acc[4][4][4];
    #pragma unroll
    for (int i = 0; i < 4; i++)
        #pragma unroll
        for (int j = 0; j < 4; j++)
            #pragma unroll
            for (int e = 0; e < 4; e++) acc[i][j][e] = 0.0f;

    const __half* Ap = A + (size_t)(m0 + tid) * K;
    const int bRowL  = tid >> 2, bQ = tid & 3;
    const __half* Wp = Wt + (size_t)(n0 + bRowL) * K + bQ * 8;

    const uint32_t sA = smem_u32(As), sB = smem_u32(Bs);
    const uint32_t aDst0 = sA + tid * 80;
    const uint32_t bDst0 = sB + (bRowL * 40 + bQ * 8) * 2;

    const int aRow  = lane & 15;
    const int aCol8 = (lane >> 4) << 3;
    const int bRow  = ((lane & 16) >> 1) + (lane & 7);
    const int bCol8 = lane & 8;
    const uint32_t aOff = ((wm + aRow) * 40 + aCol8) << 1;
    const uint32_t bOff = ((wn + bRow) * 40 + bCol8) << 1;

    const int nc = K >> 5;

    #pragma unroll
    for (int s = 0; s < 4; s++) cpa16(aDst0 + s * 16, Ap + s * 8);
    cpa16(bDst0, Wp);
    asm volatile("cp.async.commit_group;" ::: "memory");

    for (int c = 0; c < nc; c++) {
        const int buf = c & 1;
        if (c + 1 < nc) {
            const int nb = (c + 1) & 1;
            const uint32_t aD = aDst0 + nb * (256 * 80);
            const uint32_t bD = bDst0 + nb * (64 * 80);
            const __half* Ag = Ap + (c + 1) * 32;
            const __half* Wg = Wp + (c + 1) * 32;
            #pragma unroll
            for (int s = 0; s < 4; s++) cpa16(aD + s * 16, Ag + s * 8);
            cpa16(bD, Wg);
            asm volatile("cp.async.commit_group;" ::: "memory");
            asm volatile("cp.async.wait_group 1;" ::: "memory");
        } else {
            asm volatile("cp.async.wait_group 0;" ::: "memory");
        }
        __syncthreads();

        const uint32_t aBase = sA + buf * (256 * 80) + aOff;
        const uint32_t bBase = sB + buf * (64 * 80) + bOff;
        #pragma unroll
        for (int kk = 0; kk < 2; kk++) {
            uint32_t af[4][4];
            #pragma unroll
            for (int i = 0; i < 4; i++)
                ldsm4(af[i][0], af[i][1], af[i][2], af[i][3],
                      aBase + ((i * 16 * 40 + kk * 16) << 1));
            uint32_t bf[4][2];
            ldsm4(bf[0][0], bf[0][1], bf[1][0], bf[1][1], bBase + ((kk * 16) << 1));
            ldsm4(bf[2][0], bf[2][1], bf[3][0], bf[3][1], bBase + ((16 * 40 + kk * 16) << 1));
            #pragma unroll
            for (int i = 0; i < 4; i++)
                #pragma unroll
                for (int j = 0; j < 4; j++)
                    mma_f16(acc[i][j], af[i], bf[j]);
        }
        __syncthreads();
    }

    #pragma unroll
    for (int i = 0; i < 4; i++) {
        #pragma unroll
        for (int half = 0; half < 2; half++) {
            const int row = m0 + wm + (i << 4) + gp + (half << 3);
            size_t rowoff;
            if (EPI == 2) {
                int wi2 = row / Nn, nn2 = row - wi2 * Nn;
                int bi = wi2 >> 6, wl = wi2 & 63;
                int wr = wl >> 3, wc = wl & 7;
                int rr = DIV7(nn2), cc = nn2 - rr * 7;
                int hd = (wr * 7 + rr + SS) % Hh;
                int wd = (wc * 7 + cc + SS) % Ww;
                rowoff = ((size_t)bi * (Hh * Ww) + hd * Ww + wd) * (size_t)Nc;
            } else {
                rowoff = (size_t)row * Nc;
            }
            #pragma unroll
            for (int j = 0; j < 4; j++) {
                const int ncol = n0 + wn + (j << 3) + (tg << 1);
                float v0 = acc[i][j][half * 2 + 0] + bias[ncol + 0] + resid[rowoff + ncol + 0];
                float v1 = acc[i][j][half * 2 + 1] + bias[ncol + 1] + resid[rowoff + ncol + 1];
                *(float2*)((float*)Cout + rowoff + ncol) = make_float2(v0, v1);
                if (EPI == 2)
                    *(__half2*)(g_h16 + rowoff + ncol) = __floats2half2_rn(v0, v1);
            }
        }
    }
}

// ---------------- tensor-core window attention: block = (window, head), 128 thr ----------------
__global__ void __launch_bounds__(128)
attn_k() {
    __shared__ __half Qs[64 * 40];
    __shared__ __half Ks[64 * 40];
    __shared__ __half Vt[32 * 72];

    const int wi = blockIdx.x;
    const int nh = blockIdx.y;
    const int tid = threadIdx.x;
    const int wid = tid >> 5, lane = tid & 31;
    const int gp = lane >> 2, tg = lane & 3;

    const int wl = wi & 63;
    const int cls = (((wl >> 3) == 7) ? 2 : 0) | (((wl & 7) == 7) ? 1 : 0);
    const float* tp = g_tab + (cls * NHd + nh) * 4096;

    for (int idx = tid; idx < 64 * 4; idx += 128) {
        int row = idx >> 2, seg = idx & 3;
        uint4 zq = make_uint4(0, 0, 0, 0), zk = zq;
        if (row < Nn) {
            const __half* base = g_qkv16 + (size_t)(wi * Nn + row) * (3 * Cc) + nh * HD + seg * 8;
            zq = *(const uint4*)(base);
            zk = *(const uint4*)(base + Cc);
        }
        *(uint4*)(Qs + row * 40 + seg * 8) = zq;
        *(uint4*)(Ks + row * 40 + seg * 8) = zk;
    }
    for (int idx = tid; idx < 64 * 16; idx += 128) {
        int row = idx >> 4, p = idx & 15;
        __half2 v = __float2half2_rn(0.0f);
        if (row < Nn)
            v = *(const __half2*)(g_qkv16 + (size_t)(wi * Nn + row) * (3 * Cc) + 2 * Cc + nh * HD + 2 * p);
        Vt[(2 * p) * 72 + row]     = __low2half(v);
        Vt[(2 * p + 1) * 72 + row] = __high2half(v);
    }

    const int rowL = wid * 16 + gp, rowH = rowL + 8;
    float st[8][4];
    #pragma unroll
    for (int j = 0; j < 8; j++) {
        float2 vL = *(const float2*)(tp + rowL * 64 + j * 8 + tg * 2);
        float2 vH = *(const float2*)(tp + rowH * 64 + j * 8 + tg * 2);
        st[j][0] = vL.x; st[j][1] = vL.y;
        st[j][2] = vH.x; st[j][3] = vH.y;
    }
    __syncthreads();

    const int aRow  = lane & 15;
    const int aCol8 = (lane >> 4) << 3;
    const int bRow  = ((lane & 16) >> 1) + (lane & 7);
    const int bCol8 = lane & 8;
    const uint32_t qBase = smem_u32(Qs) + (((wid * 16 + aRow) * 40 + aCol8) << 1);
    const uint32_t kBase = smem_u32(Ks) + ((bRow * 40 + bCol8) << 1);

    #pragma unroll
    for (int kk = 0; kk < 2; kk++) {
        uint32_t af[4];
        ldsm4(af[0], af[1], af[2], af[3], qBase + (kk * 16 << 1));
        #pragma unroll
        for (int j2 = 0; j2 < 4; j2++) {
            uint32_t bf[2][2];
            ldsm4(bf[0][0], bf[0][1], bf[1][0], bf[1][1],
                  kBase + ((j2 * 16 * 40 + kk * 16) << 1));
            mma_f16(st[2 * j2],     af, bf[0]);
            mma_f16(st[2 * j2 + 1], af, bf[1]);
        }
    }

    #pragma unroll
    for (int hrow = 0; hrow < 2; hrow++) {
        float mx = -1e30f;
        #pragma unroll
        for (int j = 0; j < 8; j++) {
            mx = fmaxf(mx, st[j][hrow * 2]);
            mx = fmaxf(mx, st[j][hrow * 2 + 1]);
        }
        mx = fmaxf(mx, __shfl_xor_sync(0xffffffffu, mx, 1));
        mx = fmaxf(mx, __shfl_xor_sync(0xffffffffu, mx, 2));
        float sm = 0.0f;
        #pragma unroll
        for (int j = 0; j < 8; j++) {
            #pragma unroll
            for (int e = 0; e < 2; e++) {
                float ev = __expf(st[j][hrow * 2 + e] - mx);
                st[j][hrow * 2 + e] = ev;
                sm += ev;
            }
        }
        sm += __shfl_xor_sync(0xffffffffu, sm, 1);
        sm += __shfl_xor_sync(0xffffffffu, sm, 2);
        float inv = 1.0f / sm;
        #pragma unroll
        for (int j = 0; j < 8; j++) {
            st[j][hrow * 2] *= inv;
            st[j][hrow * 2 + 1] *= inv;
        }
    }

    float o[4][4];
    #pragma unroll
    for (int jt = 0; jt < 4; jt++)
        #pragma unroll
        for (int e = 0; e < 4; e++) o[jt][e] = 0.0f;

    const uint32_t vBase = smem_u32(Vt) + ((bRow * 72 + bCol8) << 1);
    #pragma unroll
    for (int kk = 0; kk < 4; kk++) {
        uint32_t a[4];
        a[0] = h2u(st[2 * kk][0],     st[2 * kk][1]);
        a[1] = h2u(st[2 * kk][2],     st[2 * kk][3]);
        a[2] = h2u(st[2 * kk + 1][0], st[2 * kk + 1][1]);
        a[3] = h2u(st[2 * kk + 1][2], st[2 * kk + 1][3]);
        #pragma unroll
        for (int jj2 = 0; jj2 < 2; jj2++) {
            uint32_t bf[2][2];
            ldsm4(bf[0][0], bf[0][1], bf[1][0], bf[1][1],
                  vBase + ((jj2 * 16 * 72 + kk * 16) << 1));
            mma_f16(o[2 * jj2],     a, bf[0]);
            mma_f16(o[2 * jj2 + 1], a, bf[1]);
        }
    }

    __half* outp = g_attn16 + (size_t)wi * Nn * Cc + nh * HD;
    #pragma unroll
    for (int hrow = 0; hrow < 2; hrow++) {
        const int rI = hrow ? rowH : rowL;
        if (rI < Nn) {
            __half* rp = outp + (size_t)rI * Cc;
            #pragma unroll
            for (int jt = 0; jt < 4; jt++)
                *(__half2*)(rp + jt * 8 + tg * 2) =
                    __floats2half2_rn(o[jt][hrow * 2], o[jt][hrow * 2 + 1]);
        }
    }
}

// ---------------- host ----------------
extern "C" void kernel_launch(void* const* d_in, const int* in_sizes, int n_in,
                              void* d_out, int out_size) {
    const float* x     = (const float*)d_in[0];
    const float* n1g   = (const float*)d_in[1];
    const float* n1b   = (const float*)d_in[2];
    const float* qkvw  = (const float*)d_in[3];
    const float* qkvb  = (const float*)d_in[4];
    const float* projw = (const float*)d_in[5];
    const float* projb = (const float*)d_in[6];
    const float* rpb   = (const float*)d_in[7];
    const float* n2g   = (const float*)d_in[8];
    const float* n2b   = (const float*)d_in[9];
    const float* fc1w  = (const float*)d_in[10];
    const float* fc1b  = (const float*)d_in[11];
    const float* fc2w  = (const float*)d_in[12];
    const float* fc2b  = (const float*)d_in[13];
    float* out = (float*)d_out;

    static __half *p_qkv16 = nullptr, *p_attn16, *p_h16, *p_act16,
                  *p_qkvw16, *p_projw16, *p_fc1w16, *p_fc2w16;
    static float *p_h;
    if (!p_qkv16) {
        cudaGetSymbolAddress((void**)&p_qkv16,  g_qkv16);
        cudaGetSymbolAddress((void**)&p_attn16, g_attn16);
        cudaGetSymbolAddress((void**)&p_h,      g_h);
        cudaGetSymbolAddress((void**)&p_h16,    g_h16);
        cudaGetSymbolAddress((void**)&p_act16,  g_act16);
        cudaGetSymbolAddress((void**)&p_qkvw16, g_qkvw16);
        cudaGetSymbolAddress((void**)&p_projw16,g_projw16);
        cudaGetSymbolAddress((void**)&p_fc1w16, g_fc1w16);
        cudaGetSymbolAddress((void**)&p_fc2w16, g_fc2w16);
        cudaFuncSetAttribute((const void*)gemm_kr<9, 0>,  cudaFuncAttributeMaxDynamicSharedMemorySize, KR_SMEM);
        cudaFuncSetAttribute((const void*)gemm_kr<12, 1>, cudaFuncAttributeMaxDynamicSharedMemorySize, KR_SMEM);
    }

    // 0) weight conversion + bias/mask tables (one launch)
    const int CV = 3 * Cc * Cc + Cc * Cc + HID * Cc + Cc * HID + 24 * 4096;
    cvt_all<<<(CV + 255) / 256, 256>>>(qkvw, projw, fc1w, fc2w, rpb);

    // 1) QKV GEMM (K-resident-A; fused LN1 + roll + window partition; Q*SCALE)
    gemm_kr<9, 0><<<TOK / 256, 256, KR_SMEM>>>(x, p_qkvw16, qkvb, n1g, n1b, p_qkv16);
    // 2) window attention
    attn_k<<<dim3(NWTOT, NHd), 128>>>();
    // 3) proj GEMM + scatter + residual -> h fp32 + h16 fp16 (b256)
    gemm_b256<2><<<dim3(3, TOK / 256), 256>>>(p_attn16, p_projw16, projb, x, p_h, Cc, Cc);
    // 4) FC1 (K-resident-A; fused LN2) + GELU -> fp16
    gemm_kr<12, 1><<<TOK / 256, 256, KR_SMEM>>>(p_h16, p_fc1w16, fc1b, n2g, n2b, p_act16);
    // 5) FC2 + residual -> out (b256)
    gemm_b256<3><<<dim3(3, TOK / 256), 256>>>(p_act16, p_fc2w16, fc2b, p_h, out, Cc, HID);
}